// round 1
// baseline (speedup 1.0000x reference)
#include <cuda_runtime.h>
#include <cuda_bf16.h>

#define N 8192
#define ROWLEN 85
#define NCLS 80
#define CAP 1024

__device__ unsigned long long g_keys[N];
__device__ int g_cat[N];
__device__ int g_order[N];
__device__ int g_keep[N];

// ---------------------------------------------------------------------------
// K1: per-row class argmax + combined score, build stable sort key.
// warp per row: lanes cover class indices lane, lane+32, lane+64.
// ---------------------------------------------------------------------------
__global__ void score_kernel(const float* __restrict__ X) {
    int warp = (blockIdx.x * blockDim.x + threadIdx.x) >> 5;
    int lane = threadIdx.x & 31;
    if (warp >= N) return;
    const float* row = X + (long)warp * ROWLEN;

    float best = -1.0f;
    int bi = 0x7fffffff;
    #pragma unroll
    for (int c = lane; c < NCLS; c += 32) {
        float v = row[5 + c];
        if (v > best) { best = v; bi = c; }   // strict > keeps first occurrence
    }
    #pragma unroll
    for (int off = 16; off; off >>= 1) {
        float ov = __shfl_down_sync(0xffffffffu, best, off);
        int   oi = __shfl_down_sync(0xffffffffu, bi, off);
        if (ov > best || (ov == best && oi < bi)) { best = ov; bi = oi; }
    }
    if (lane == 0) {
        float score = row[4] * best;                  // nonnegative
        unsigned bits = __float_as_uint(score);       // monotone for >= 0
        g_keys[warp] = ((unsigned long long)(~bits) << 32) | (unsigned)warp;
        g_cat[warp] = bi;
    }
}

// ---------------------------------------------------------------------------
// K2: single-block bitonic sort of 8192 u64 keys (ascending).
// Ascending key = descending score, ties broken by ascending original index
// (== stable argsort of -scores).
// ---------------------------------------------------------------------------
__global__ void sort_kernel() {
    extern __shared__ unsigned long long s[];
    for (int i = threadIdx.x; i < N; i += blockDim.x) s[i] = g_keys[i];
    __syncthreads();
    for (int k = 2; k <= N; k <<= 1) {
        for (int j = k >> 1; j > 0; j >>= 1) {
            for (int i = threadIdx.x; i < N; i += blockDim.x) {
                int ixj = i ^ j;
                if (ixj > i) {
                    bool up = ((i & k) == 0);
                    unsigned long long a = s[i], b = s[ixj];
                    if ((a > b) == up) { s[i] = b; s[ixj] = a; }
                }
            }
            __syncthreads();
        }
    }
    for (int i = threadIdx.x; i < N; i += blockDim.x)
        g_order[i] = (int)(s[i] & 0xFFFFFFFFull);
}

// ---------------------------------------------------------------------------
// K3: per-class greedy NMS. One block (1 warp) per class.
// Class offsets in the reference guarantee zero cross-class IoU, so greedy
// suppression decomposes exactly per class with raw (un-offset) boxes.
// ---------------------------------------------------------------------------
__global__ void nms_kernel(const float* __restrict__ X) {
    __shared__ float sx1[CAP], sy1[CAP], sx2[CAP], sy2[CAP], sa[CAP];
    __shared__ int spos[CAP];
    __shared__ unsigned ssup[CAP / 32];

    int c = blockIdx.x;
    int lane = threadIdx.x;

    // order-preserving compaction of this class's entries from sorted order
    int cnt = 0;
    for (int base = 0; base < N; base += 32) {
        int sidx = g_order[base + lane];
        bool pred = (g_cat[sidx] == c);
        unsigned mask = __ballot_sync(0xffffffffu, pred);
        if (pred) {
            int slot = cnt + __popc(mask & ((1u << lane) - 1u));
            if (slot < CAP) {
                const float* row = X + (long)sidx * ROWLEN;
                float x1 = row[0], y1 = row[1], x2 = row[2], y2 = row[3];
                sx1[slot] = x1; sy1[slot] = y1; sx2[slot] = x2; sy2[slot] = y2;
                sa[slot] = (x2 - x1) * (y2 - y1);
                spos[slot] = base + lane;
            }
        }
        cnt += __popc(mask);
    }
    int m = min(cnt, CAP);

    for (int w = lane; w < CAP / 32; w += 32) ssup[w] = 0u;
    __syncwarp();

    // greedy: sequential over i (score order), lane-parallel over j > i
    for (int i = 0; i < m; ++i) {
        if ((ssup[i >> 5] >> (i & 31)) & 1u) continue;
        float x1 = sx1[i], y1 = sy1[i], x2 = sx2[i], y2 = sy2[i], ai = sa[i];
        for (int j = i + 1 + lane; j < m; j += 32) {
            float xx1 = fmaxf(x1, sx1[j]);
            float yy1 = fmaxf(y1, sy1[j]);
            float xx2 = fminf(x2, sx2[j]);
            float yy2 = fminf(y2, sy2[j]);
            float w = fmaxf(xx2 - xx1, 0.0f);
            float h = fmaxf(yy2 - yy1, 0.0f);
            float inter = w * h;
            float iou = inter / (ai + sa[j] - inter);
            if (iou > 0.5f) atomicOr(&ssup[j >> 5], 1u << (j & 31));
        }
        __syncwarp();
    }

    for (int r = lane; r < m; r += 32)
        g_keep[spos[r]] = ((ssup[r >> 5] >> (r & 31)) & 1u) ? 0 : 1;
}

// ---------------------------------------------------------------------------
// K4: gather rows in sorted order, zero suppressed rows.
// ---------------------------------------------------------------------------
__global__ void gather_kernel(const float* __restrict__ X, float* __restrict__ out) {
    int r = blockIdx.x;
    int src = g_order[r];
    float k = (float)g_keep[r];
    int t = threadIdx.x;
    if (t < ROWLEN)
        out[(long)r * ROWLEN + t] = X[(long)src * ROWLEN + t] * k;
}

// ---------------------------------------------------------------------------
extern "C" void kernel_launch(void* const* d_in, const int* in_sizes, int n_in,
                              void* d_out, int out_size) {
    const float* X = (const float*)d_in[0];
    float* out = (float*)d_out;

    cudaFuncSetAttribute(sort_kernel,
                         cudaFuncAttributeMaxDynamicSharedMemorySize,
                         N * sizeof(unsigned long long));

    score_kernel<<<N / 8, 256>>>(X);                                  // 8 warps/block
    sort_kernel<<<1, 1024, N * sizeof(unsigned long long)>>>();
    nms_kernel<<<NCLS, 32>>>(X);
    gather_kernel<<<N, 96>>>(X, out);
}

// round 2
// speedup vs baseline: 1.2742x; 1.2742x over previous
#include <cuda_runtime.h>
#include <cuda_bf16.h>

#define N 8192
#define ROWLEN 85
#define NCLS 80
#define CAP 1024

__device__ unsigned long long g_keys[N];
__device__ int g_cat[N];
__device__ int g_order[N];
__device__ int g_cats[N];   // g_cat gathered into sorted order
__device__ int g_keep[N];

// ---------------------------------------------------------------------------
// K1: per-row class argmax + combined score, build stable sort key.
// ---------------------------------------------------------------------------
__global__ void score_kernel(const float* __restrict__ X) {
    int warp = (blockIdx.x * blockDim.x + threadIdx.x) >> 5;
    int lane = threadIdx.x & 31;
    if (warp >= N) return;
    const float* row = X + (long)warp * ROWLEN;

    float best = -1.0f;
    int bi = 0x7fffffff;
    #pragma unroll
    for (int c = lane; c < NCLS; c += 32) {
        float v = row[5 + c];
        if (v > best) { best = v; bi = c; }
    }
    #pragma unroll
    for (int off = 16; off; off >>= 1) {
        float ov = __shfl_down_sync(0xffffffffu, best, off);
        int   oi = __shfl_down_sync(0xffffffffu, bi, off);
        if (ov > best || (ov == best && oi < bi)) { best = ov; bi = oi; }
    }
    if (lane == 0) {
        float score = row[4] * best;                  // nonnegative
        unsigned bits = __float_as_uint(score);       // monotone for >= 0
        g_keys[warp] = ((unsigned long long)(~bits) << 32) | (unsigned)warp;
        g_cat[warp] = bi;
    }
}

// ---------------------------------------------------------------------------
// Hierarchical bitonic sort (ascending u64 == descending score, stable).
// The network compare-exchanges (i, i^j) with direction (i & k)==0; it is
// data-independent, so stages split across kernels freely.
// ---------------------------------------------------------------------------

// Full bitonic sort of each 2048-aligned chunk (k = 2..2048). 4 blocks.
__global__ void sort_local_full() {
    __shared__ unsigned long long s[2048];
    int base = blockIdx.x * 2048;
    int t = threadIdx.x;                      // 1024 threads
    s[t]        = g_keys[base + t];
    s[t + 1024] = g_keys[base + t + 1024];
    __syncthreads();
    for (int k = 2; k <= 2048; k <<= 1) {
        for (int j = k >> 1; j > 0; j >>= 1) {
            int i = ((t & ~(j - 1)) << 1) | (t & (j - 1));
            bool up = (((base + i) & k) == 0);
            unsigned long long a = s[i], b = s[i | j];
            if ((a > b) == up) { s[i] = b; s[i | j] = a; }
            __syncthreads();
        }
    }
    g_keys[base + t]        = s[t];
    g_keys[base + t + 1024] = s[t + 1024];
}

// One global compare-exchange pass for (k, j) with j >= 2048. 4096 pairs.
__global__ void sort_global(int k, int j) {
    int t = blockIdx.x * blockDim.x + threadIdx.x;       // 0..4095
    int i = ((t & ~(j - 1)) << 1) | (t & (j - 1));
    bool up = ((i & k) == 0);
    unsigned long long a = g_keys[i], b = g_keys[i | j];
    if ((a > b) == up) { g_keys[i] = b; g_keys[i | j] = a; }
}

// Local merge: stages j = 1024..1 for merge step k, within each 2048 chunk.
// When finalize != 0 this is the last stage: emit order + sorted categories.
__global__ void sort_local_merge(int k, int finalize) {
    __shared__ unsigned long long s[2048];
    int base = blockIdx.x * 2048;
    int t = threadIdx.x;
    s[t]        = g_keys[base + t];
    s[t + 1024] = g_keys[base + t + 1024];
    __syncthreads();
    for (int j = 1024; j > 0; j >>= 1) {
        int i = ((t & ~(j - 1)) << 1) | (t & (j - 1));
        bool up = (((base + i) & k) == 0);
        unsigned long long a = s[i], b = s[i | j];
        if ((a > b) == up) { s[i] = b; s[i | j] = a; }
        __syncthreads();
    }
    if (finalize) {
        int i0 = (int)(s[t] & 0xFFFFFFFFull);
        int i1 = (int)(s[t + 1024] & 0xFFFFFFFFull);
        g_order[base + t] = i0;
        g_order[base + t + 1024] = i1;
        g_cats[base + t] = g_cat[i0];
        g_cats[base + t + 1024] = g_cat[i1];
    } else {
        g_keys[base + t]        = s[t];
        g_keys[base + t + 1024] = s[t + 1024];
    }
}

// ---------------------------------------------------------------------------
// K3: per-class greedy NMS. One warp per class. Class offsets in the reference
// make cross-class IoU exactly 0, so suppression decomposes per class.
// ---------------------------------------------------------------------------
__global__ void nms_kernel(const float* __restrict__ X) {
    __shared__ float sx1[CAP], sy1[CAP], sx2[CAP], sy2[CAP], sa[CAP];
    __shared__ int spos[CAP];
    __shared__ unsigned ssup[CAP / 32];

    int c = blockIdx.x;
    int lane = threadIdx.x;

    // order-preserving compaction of this class's entries (contiguous g_cats)
    int cnt = 0;
    for (int base = 0; base < N; base += 32) {
        bool pred = (g_cats[base + lane] == c);
        unsigned mask = __ballot_sync(0xffffffffu, pred);
        if (pred) {
            int slot = cnt + __popc(mask & ((1u << lane) - 1u));
            if (slot < CAP) {
                int sidx = g_order[base + lane];
                const float* row = X + (long)sidx * ROWLEN;
                float x1 = row[0], y1 = row[1], x2 = row[2], y2 = row[3];
                sx1[slot] = x1; sy1[slot] = y1; sx2[slot] = x2; sy2[slot] = y2;
                sa[slot] = (x2 - x1) * (y2 - y1);
                spos[slot] = base + lane;
            }
        }
        cnt += __popc(mask);
    }
    int m = min(cnt, CAP);

    for (int w = lane; w < CAP / 32; w += 32) ssup[w] = 0u;
    __syncwarp();

    for (int i = 0; i < m; ++i) {
        if ((ssup[i >> 5] >> (i & 31)) & 1u) continue;
        float x1 = sx1[i], y1 = sy1[i], x2 = sx2[i], y2 = sy2[i], ai = sa[i];
        for (int j = i + 1 + lane; j < m; j += 32) {
            float xx1 = fmaxf(x1, sx1[j]);
            float yy1 = fmaxf(y1, sy1[j]);
            float xx2 = fminf(x2, sx2[j]);
            float yy2 = fminf(y2, sy2[j]);
            float w = fmaxf(xx2 - xx1, 0.0f);
            float h = fmaxf(yy2 - yy1, 0.0f);
            float inter = w * h;
            float iou = inter / (ai + sa[j] - inter);
            if (iou > 0.5f) atomicOr(&ssup[j >> 5], 1u << (j & 31));
        }
        __syncwarp();
    }

    for (int r = lane; r < m; r += 32)
        g_keep[spos[r]] = ((ssup[r >> 5] >> (r & 31)) & 1u) ? 0 : 1;
}

// ---------------------------------------------------------------------------
// K4: element-parallel gather: one thread per output float.
// ---------------------------------------------------------------------------
__global__ void gather_kernel(const float* __restrict__ X, float* __restrict__ out) {
    int idx = blockIdx.x * blockDim.x + threadIdx.x;
    if (idx >= N * ROWLEN) return;
    int r = idx / ROWLEN;
    int col = idx - r * ROWLEN;
    int src = __ldg(&g_order[r]);
    float k = (float)__ldg(&g_keep[r]);
    out[idx] = X[(long)src * ROWLEN + col] * k;
}

// ---------------------------------------------------------------------------
extern "C" void kernel_launch(void* const* d_in, const int* in_sizes, int n_in,
                              void* d_out, int out_size) {
    const float* X = (const float*)d_in[0];
    float* out = (float*)d_out;

    score_kernel<<<N / 8, 256>>>(X);

    sort_local_full<<<4, 1024>>>();
    sort_global<<<4, 1024>>>(4096, 2048);
    sort_local_merge<<<4, 1024>>>(4096, 0);
    sort_global<<<4, 1024>>>(8192, 4096);
    sort_global<<<4, 1024>>>(8192, 2048);
    sort_local_merge<<<4, 1024>>>(8192, 1);

    nms_kernel<<<NCLS, 32>>>(X);

    int total = N * ROWLEN;
    gather_kernel<<<(total + 255) / 256, 256>>>(X, out);
}

// round 3
// speedup vs baseline: 2.7147x; 2.1306x over previous
#include <cuda_runtime.h>
#include <cuda_bf16.h>

#define N 8192
#define ROWLEN 85
#define NCLS 80
#define CAP 384
#define MW 12            // CAP/32 mask words per row

__device__ unsigned long long g_keys[N];
__device__ int g_cat[N];
__device__ int g_order[N];
__device__ int g_cats[N];   // categories in sorted order
__device__ int g_keep[N];

// ---------------------------------------------------------------------------
// K1: per-row class argmax + combined score -> stable sort key.
// ---------------------------------------------------------------------------
__global__ void score_kernel(const float* __restrict__ X) {
    int warp = (blockIdx.x * blockDim.x + threadIdx.x) >> 5;
    int lane = threadIdx.x & 31;
    if (warp >= N) return;
    const float* row = X + (long)warp * ROWLEN;

    float best = -1.0f;
    int bi = 0x7fffffff;
    #pragma unroll
    for (int c = lane; c < NCLS; c += 32) {
        float v = row[5 + c];
        if (v > best) { best = v; bi = c; }
    }
    #pragma unroll
    for (int off = 16; off; off >>= 1) {
        float ov = __shfl_down_sync(0xffffffffu, best, off);
        int   oi = __shfl_down_sync(0xffffffffu, bi, off);
        if (ov > best || (ov == best && oi < bi)) { best = ov; bi = oi; }
    }
    if (lane == 0) {
        float score = row[4] * best;                 // nonnegative
        unsigned bits = __float_as_uint(score);      // monotone for >= 0
        g_keys[warp] = ((unsigned long long)(~bits) << 32) | (unsigned)warp;
        g_cat[warp] = bi;
    }
}

// ---------------------------------------------------------------------------
// K2: single-block bitonic sort of 8192 u64 keys (ascending == score desc,
// stable by index). Each thread owns 8 consecutive elements; all network
// steps with j<8 run in registers, collapsing barrier rounds 91 -> ~66.
// ---------------------------------------------------------------------------
__device__ __forceinline__ void ce(unsigned long long& a, unsigned long long& b, bool up) {
    if ((a > b) == up) { unsigned long long t = a; a = b; b = t; }
}

__global__ void sort_kernel() {
    extern __shared__ unsigned long long s[];
    int t = threadIdx.x;               // 1024 threads
    int base = t * 8;

    for (int i = t; i < N; i += 1024) s[i] = g_keys[i];
    __syncthreads();

    // Initial k=2,4,8 entirely in registers (direction varies per pair).
    {
        unsigned long long e[8];
        #pragma unroll
        for (int l = 0; l < 8; l++) e[l] = s[base + l];
        // k=2, j=1
        ce(e[0], e[1], ((base + 0) & 2) == 0);
        ce(e[2], e[3], ((base + 2) & 2) == 0);
        ce(e[4], e[5], ((base + 4) & 2) == 0);
        ce(e[6], e[7], ((base + 6) & 2) == 0);
        // k=4, j=2
        ce(e[0], e[2], ((base + 0) & 4) == 0);
        ce(e[1], e[3], ((base + 1) & 4) == 0);
        ce(e[4], e[6], ((base + 4) & 4) == 0);
        ce(e[5], e[7], ((base + 5) & 4) == 0);
        // k=4, j=1
        ce(e[0], e[1], ((base + 0) & 4) == 0);
        ce(e[2], e[3], ((base + 2) & 4) == 0);
        ce(e[4], e[5], ((base + 4) & 4) == 0);
        ce(e[6], e[7], ((base + 6) & 4) == 0);
        // k=8: direction constant within the 8-block
        bool up8 = ((base & 8) == 0);
        ce(e[0], e[4], up8); ce(e[1], e[5], up8); ce(e[2], e[6], up8); ce(e[3], e[7], up8);
        ce(e[0], e[2], up8); ce(e[1], e[3], up8); ce(e[4], e[6], up8); ce(e[5], e[7], up8);
        ce(e[0], e[1], up8); ce(e[2], e[3], up8); ce(e[4], e[5], up8); ce(e[6], e[7], up8);
        #pragma unroll
        for (int l = 0; l < 8; l++) s[base + l] = e[l];
    }
    __syncthreads();

    for (int k = 16; k <= N; k <<= 1) {
        // cross-thread steps j = k/2 .. 8 via smem
        for (int j = k >> 1; j >= 8; j >>= 1) {
            #pragma unroll
            for (int q = 0; q < 4; q++) {
                int p = t + q * 1024;                       // 4096 pairs total
                int i = ((p & ~(j - 1)) << 1) | (p & (j - 1));
                bool up = ((i & k) == 0);
                unsigned long long a = s[i], b = s[i | j];
                if ((a > b) == up) { s[i] = b; s[i | j] = a; }
            }
            __syncthreads();
        }
        // j = 4,2,1 cascade in registers (direction constant for k>=16)
        {
            unsigned long long e[8];
            #pragma unroll
            for (int l = 0; l < 8; l++) e[l] = s[base + l];
            bool up = ((base & k) == 0);
            ce(e[0], e[4], up); ce(e[1], e[5], up); ce(e[2], e[6], up); ce(e[3], e[7], up);
            ce(e[0], e[2], up); ce(e[1], e[3], up); ce(e[4], e[6], up); ce(e[5], e[7], up);
            ce(e[0], e[1], up); ce(e[2], e[3], up); ce(e[4], e[5], up); ce(e[6], e[7], up);
            #pragma unroll
            for (int l = 0; l < 8; l++) s[base + l] = e[l];
        }
        __syncthreads();
    }

    for (int i = t; i < N; i += 1024) {
        int idx = (int)(s[i] & 0xFFFFFFFFull);
        g_order[i] = idx;
        g_cats[i] = g_cat[idx];
    }
}

// ---------------------------------------------------------------------------
// K3: per-class greedy NMS, one block of 256 threads per class.
// Class offsets in the reference make cross-class IoU exactly 0, so greedy
// suppression decomposes per class with raw boxes.
// Phase A: order-preserving compaction (all cats prefetched in one MLP burst).
// Phase B: parallel m x m IoU suppression-bitmask build.
// Phase C: warp-serial greedy bit-merge (exact reference semantics).
// ---------------------------------------------------------------------------
__global__ void nms_kernel(const float* __restrict__ X) {
    __shared__ float4 sb[CAP];
    __shared__ float sa[CAP];
    __shared__ int spos[CAP];
    __shared__ unsigned smask[CAP * MW];
    __shared__ unsigned ssup[MW];
    __shared__ int wcnt[8];

    int c = blockIdx.x;
    int t = threadIdx.x, lane = t & 31, w = t >> 5;

    // Phase A: front-load all 32 category values (independent loads, MLP)
    int cats[32];
    #pragma unroll
    for (int q = 0; q < 32; q++) cats[q] = g_cats[q * 256 + t];

    int run = 0;
    #pragma unroll
    for (int q = 0; q < 32; q++) {
        bool pred = (cats[q] == c);
        unsigned mk = __ballot_sync(0xffffffffu, pred);
        if (lane == 0) wcnt[w] = __popc(mk);
        __syncthreads();
        int prefix = run;
        #pragma unroll
        for (int k = 0; k < 8; k++) {
            int v = wcnt[k];
            if (k < w) prefix += v;
            run += v;
        }
        if (pred) {
            int slot = prefix + __popc(mk & ((1u << lane) - 1u));
            if (slot < CAP) spos[slot] = q * 256 + t;
        }
        __syncthreads();
    }
    int m = min(run, CAP);
    int mw = (m + 31) >> 5;

    // load boxes for this class (coalesced over slots)
    for (int r = t; r < m; r += 256) {
        int sidx = g_order[spos[r]];
        const float* row = X + (long)sidx * ROWLEN;
        float x1 = row[0], y1 = row[1], x2 = row[2], y2 = row[3];
        sb[r] = make_float4(x1, y1, x2, y2);
        sa[r] = (x2 - x1) * (y2 - y1);
    }
    for (int p = t; p < m * MW; p += 256) smask[p] = 0u;
    __syncthreads();

    // Phase B: mask[i] = set of j > i with IoU(i,j) > 0.5
    for (int i = w; i < m; i += 8) {
        float4 bi = sb[i];
        float ai = sa[i];
        for (int j = i + 1 + lane; j < m; j += 32) {
            float4 bj = sb[j];
            float xx1 = fmaxf(bi.x, bj.x);
            float yy1 = fmaxf(bi.y, bj.y);
            float xx2 = fminf(bi.z, bj.z);
            float yy2 = fminf(bi.w, bj.w);
            float ww = fmaxf(xx2 - xx1, 0.0f);
            float hh = fmaxf(yy2 - yy1, 0.0f);
            float inter = ww * hh;
            float iou = inter / (ai + sa[j] - inter);
            if (iou > 0.5f) atomicOr(&smask[i * MW + (j >> 5)], 1u << (j & 31));
        }
    }
    __syncthreads();

    // Phase C: serial greedy bit-merge (warp 0; lane l owns sup word l)
    if (w == 0) {
        unsigned sw = 0;
        for (int i = 0; i < m; i++) {
            unsigned word = __shfl_sync(0xffffffffu, sw, i >> 5);
            if (!((word >> (i & 31)) & 1u)) {
                if (lane < mw) sw |= smask[i * MW + lane];
            }
        }
        if (lane < MW) ssup[lane] = sw;
    }
    __syncthreads();

    for (int r = t; r < m; r += 256) {
        int keep = ((ssup[r >> 5] >> (r & 31)) & 1u) ? 0 : 1;
        g_keep[spos[r]] = keep;
    }
}

// ---------------------------------------------------------------------------
// K4: element-parallel gather: one thread per output float.
// ---------------------------------------------------------------------------
__global__ void gather_kernel(const float* __restrict__ X, float* __restrict__ out) {
    int idx = blockIdx.x * blockDim.x + threadIdx.x;
    if (idx >= N * ROWLEN) return;
    int r = idx / ROWLEN;
    int col = idx - r * ROWLEN;
    int src = __ldg(&g_order[r]);
    float k = (float)__ldg(&g_keep[r]);
    out[idx] = X[(long)src * ROWLEN + col] * k;
}

// ---------------------------------------------------------------------------
extern "C" void kernel_launch(void* const* d_in, const int* in_sizes, int n_in,
                              void* d_out, int out_size) {
    const float* X = (const float*)d_in[0];
    float* out = (float*)d_out;

    cudaFuncSetAttribute(sort_kernel,
                         cudaFuncAttributeMaxDynamicSharedMemorySize,
                         N * sizeof(unsigned long long));

    score_kernel<<<N / 8, 256>>>(X);
    sort_kernel<<<1, 1024, N * sizeof(unsigned long long)>>>();
    nms_kernel<<<NCLS, 256>>>(X);

    int total = N * ROWLEN;
    gather_kernel<<<(total + 255) / 256, 256>>>(X, out);
}

// round 4
// speedup vs baseline: 3.8077x; 1.4026x over previous
#include <cuda_runtime.h>
#include <cuda_bf16.h>
#include <cub/block/block_radix_sort.cuh>

#define N 8192
#define ROWLEN 85
#define NCLS 80
#define CAP 384
#define MW 12            // CAP/32 mask words per row

__device__ unsigned g_skey[N];   // ~float_bits(score): ascending == score desc
__device__ int g_cat[N];
__device__ int g_order[N];
__device__ int g_cats[N];        // categories in sorted order
__device__ int g_keep[N];

// ---------------------------------------------------------------------------
// K1: per-row class argmax + combined score -> 32-bit sort key.
// ---------------------------------------------------------------------------
__global__ void score_kernel(const float* __restrict__ X) {
    int warp = (blockIdx.x * blockDim.x + threadIdx.x) >> 5;
    int lane = threadIdx.x & 31;
    if (warp >= N) return;
    const float* row = X + (long)warp * ROWLEN;

    float best = -1.0f;
    int bi = 0x7fffffff;
    #pragma unroll
    for (int c = lane; c < NCLS; c += 32) {
        float v = row[5 + c];
        if (v > best) { best = v; bi = c; }
    }
    #pragma unroll
    for (int off = 16; off; off >>= 1) {
        float ov = __shfl_down_sync(0xffffffffu, best, off);
        int   oi = __shfl_down_sync(0xffffffffu, bi, off);
        if (ov > best || (ov == best && oi < bi)) { best = ov; bi = oi; }
    }
    if (lane == 0) {
        float score = row[4] * best;                 // nonnegative
        g_skey[warp] = ~__float_as_uint(score);      // monotone flip for >= 0
        g_cat[warp] = bi;
    }
}

// ---------------------------------------------------------------------------
// K2: single-block stable LSD radix sort of 8192 (key32, idx) pairs via CUB.
// Stable radix == jnp.argsort(-scores) tie semantics.
// ---------------------------------------------------------------------------
typedef cub::BlockRadixSort<unsigned, 1024, 8, unsigned> BlockSortT;

__global__ void sort_kernel() {
    extern __shared__ __align__(16) char smem_raw[];
    BlockSortT::TempStorage& temp =
        *reinterpret_cast<BlockSortT::TempStorage*>(smem_raw);

    int t = threadIdx.x;
    unsigned keys[8], vals[8];
    #pragma unroll
    for (int l = 0; l < 8; l++) {
        keys[l] = g_skey[t * 8 + l];
        vals[l] = t * 8 + l;
    }

    BlockSortT(temp).Sort(keys, vals);   // blocked arrangement, stable

    #pragma unroll
    for (int l = 0; l < 8; l++) {
        int r = t * 8 + l;
        int idx = (int)vals[l];
        g_order[r] = idx;
        g_cats[r] = g_cat[idx];
    }
}

// ---------------------------------------------------------------------------
// K3: per-class greedy NMS, one block of 256 threads per class.
// Class offsets in the reference make cross-class IoU exactly 0, so greedy
// suppression decomposes per class with raw boxes.
// ---------------------------------------------------------------------------
__global__ void nms_kernel(const float* __restrict__ X) {
    __shared__ float4 sb[CAP];
    __shared__ float sa[CAP];
    __shared__ int spos[CAP];
    __shared__ unsigned smask[CAP * MW];
    __shared__ unsigned ssup[MW];
    __shared__ int wcnt[8];

    int c = blockIdx.x;
    int t = threadIdx.x, lane = t & 31, w = t >> 5;

    // Phase A: front-load all 32 category values (one MLP burst)
    int cats[32];
    #pragma unroll
    for (int q = 0; q < 32; q++) cats[q] = g_cats[q * 256 + t];

    int run = 0;
    #pragma unroll
    for (int q = 0; q < 32; q++) {
        bool pred = (cats[q] == c);
        unsigned mk = __ballot_sync(0xffffffffu, pred);
        if (lane == 0) wcnt[w] = __popc(mk);
        __syncthreads();
        int prefix = run;
        #pragma unroll
        for (int k = 0; k < 8; k++) {
            int v = wcnt[k];
            if (k < w) prefix += v;
            run += v;
        }
        if (pred) {
            int slot = prefix + __popc(mk & ((1u << lane) - 1u));
            if (slot < CAP) spos[slot] = q * 256 + t;
        }
        __syncthreads();
    }
    int m = min(run, CAP);
    int mw = (m + 31) >> 5;

    for (int r = t; r < m; r += 256) {
        int sidx = g_order[spos[r]];
        const float* row = X + (long)sidx * ROWLEN;
        float x1 = row[0], y1 = row[1], x2 = row[2], y2 = row[3];
        sb[r] = make_float4(x1, y1, x2, y2);
        sa[r] = (x2 - x1) * (y2 - y1);
    }
    for (int p = t; p < m * MW; p += 256) smask[p] = 0u;
    __syncthreads();

    // Phase B: mask[i] = set of j > i with IoU(i,j) > 0.5
    for (int i = w; i < m; i += 8) {
        float4 bi = sb[i];
        float ai = sa[i];
        for (int j = i + 1 + lane; j < m; j += 32) {
            float4 bj = sb[j];
            float xx1 = fmaxf(bi.x, bj.x);
            float yy1 = fmaxf(bi.y, bj.y);
            float xx2 = fminf(bi.z, bj.z);
            float yy2 = fminf(bi.w, bj.w);
            float ww = fmaxf(xx2 - xx1, 0.0f);
            float hh = fmaxf(yy2 - yy1, 0.0f);
            float inter = ww * hh;
            float iou = inter / (ai + sa[j] - inter);
            if (iou > 0.5f) atomicOr(&smask[i * MW + (j >> 5)], 1u << (j & 31));
        }
    }
    __syncthreads();

    // Phase C: serial greedy bit-merge (warp 0; lane l owns sup word l)
    if (w == 0) {
        unsigned sw = 0;
        for (int i = 0; i < m; i++) {
            unsigned word = __shfl_sync(0xffffffffu, sw, i >> 5);
            if (!((word >> (i & 31)) & 1u)) {
                if (lane < mw) sw |= smask[i * MW + lane];
            }
        }
        if (lane < MW) ssup[lane] = sw;
    }
    __syncthreads();

    for (int r = t; r < m; r += 256) {
        int keep = ((ssup[r >> 5] >> (r & 31)) & 1u) ? 0 : 1;
        g_keep[spos[r]] = keep;
    }
}

// ---------------------------------------------------------------------------
// K4: element-parallel gather, 4-way unrolled grid-stride for MLP.
// ---------------------------------------------------------------------------
__global__ void gather_kernel(const float* __restrict__ X, float* __restrict__ out) {
    const int total = N * ROWLEN;
    int stride = gridDim.x * blockDim.x;
    int idx = blockIdx.x * blockDim.x + threadIdx.x;
    #pragma unroll 4
    for (int q = 0; q < 4; q++) {
        int e = idx + q * stride;
        if (e < total) {
            int r = e / ROWLEN;
            int col = e - r * ROWLEN;
            int src = __ldg(&g_order[r]);
            float k = (float)__ldg(&g_keep[r]);
            out[e] = X[(long)src * ROWLEN + col] * k;
        }
    }
}

// ---------------------------------------------------------------------------
extern "C" void kernel_launch(void* const* d_in, const int* in_sizes, int n_in,
                              void* d_out, int out_size) {
    const float* X = (const float*)d_in[0];
    float* out = (float*)d_out;

    static int smem_set = 0;
    int sort_smem = (int)sizeof(BlockSortT::TempStorage);
    if (!smem_set) {
        cudaFuncSetAttribute(sort_kernel,
                             cudaFuncAttributeMaxDynamicSharedMemorySize,
                             sort_smem);
        smem_set = 1;
    }

    score_kernel<<<N / 8, 256>>>(X);
    sort_kernel<<<1, 1024, sort_smem>>>();
    nms_kernel<<<NCLS, 256>>>(X);

    const int total = N * ROWLEN;
    const int threads = (total + 3) / 4;
    gather_kernel<<<(threads + 255) / 256, 256>>>(X, out);
}

// round 6
// speedup vs baseline: 7.0674x; 1.8561x over previous
#include <cuda_runtime.h>
#include <cuda_bf16.h>
#include <cub/block/block_radix_sort.cuh>

#define N 8192
#define ROWLEN 85
#define NCLS 80
#define CAP 512
#define MW 16            // CAP/32 suppression-mask words
#define FT 512           // fused-kernel threads

__device__ unsigned g_skey[N];   // ~float_bits(score); ascending == score desc
__device__ unsigned g_pack[N];   // row<<7 | cat
__device__ int g_rank[N];        // original row -> sorted position (inverse perm)
__device__ float g_keepf[N];     // keep flag by original row (1.0 / 0.0)

// ---------------------------------------------------------------------------
// K1: per-row class argmax + combined score -> (key, packed row|cat).
// ---------------------------------------------------------------------------
__global__ void score_kernel(const float* __restrict__ X) {
    int warp = (blockIdx.x * blockDim.x + threadIdx.x) >> 5;
    int lane = threadIdx.x & 31;
    if (warp >= N) return;
    const float* row = X + (long)warp * ROWLEN;

    float best = -1.0f;
    int bi = 0x7fffffff;
    #pragma unroll
    for (int c = lane; c < NCLS; c += 32) {
        float v = row[5 + c];
        if (v > best) { best = v; bi = c; }
    }
    #pragma unroll
    for (int off = 16; off; off >>= 1) {
        float ov = __shfl_down_sync(0xffffffffu, best, off);
        int   oi = __shfl_down_sync(0xffffffffu, bi, off);
        if (ov > best || (ov == best && oi < bi)) { best = ov; bi = oi; }
    }
    if (lane == 0) {
        float score = row[4] * best;                 // in [0, 1)
        g_skey[warp] = ~__float_as_uint(score);      // monotone flip
        g_pack[warp] = ((unsigned)warp << 7) | (unsigned)bi;
    }
}

// ---------------------------------------------------------------------------
// K2 (fused, 512 threads): block 0 = global stable radix sort (rank output);
// blocks 1..80 = per-class greedy NMS. Class offsets in the reference make
// cross-class IoU exactly 0, so suppression decomposes per class; each class
// block compacts + locally sorts its own entries, independent of block 0.
// ---------------------------------------------------------------------------
typedef cub::BlockRadixSort<unsigned, FT, 16, unsigned, 5> BlockSortT;

struct NmsShared {
    unsigned long long keys[CAP];
    float4 box[CAP];
    float area[CAP];
    unsigned mask[CAP * MW];
    unsigned sup[MW];
    int cnt;
};

__global__ void __launch_bounds__(FT, 1)
sortnms_kernel(const float* __restrict__ X) {
    extern __shared__ __align__(16) char sm[];
    int t = threadIdx.x;

    if (blockIdx.x == 0) {
        // ----- global sort: 30 significant key bits, 6 passes of 5 bits -----
        BlockSortT::TempStorage& temp =
            *reinterpret_cast<BlockSortT::TempStorage*>(sm);
        unsigned keys[16], vals[16];
        #pragma unroll
        for (int l = 0; l < 16; l++) {
            int r = t * 16 + l;
            keys[l] = g_skey[r];
            vals[l] = g_pack[r];
        }
        BlockSortT(temp).Sort(keys, vals, 0, 30);   // stable
        #pragma unroll
        for (int l = 0; l < 16; l++) {
            g_rank[vals[l] >> 7] = t * 16 + l;      // inverse permutation
        }
        return;
    }

    // ----- per-class NMS -----
    NmsShared& S = *reinterpret_cast<NmsShared*>(sm);
    unsigned c = blockIdx.x - 1;
    int lane = t & 31, w = t >> 5;

    if (t == 0) S.cnt = 0;
    S.keys[t] = 0xFFFFFFFFFFFFFFFFull;                  // pad for bitonic
    __syncthreads();

    // compaction (order irrelevant: local sort fixes it; key64 carries row
    // index for exact stable tie-break identical to the global argsort)
    #pragma unroll
    for (int q = 0; q < N / FT; q++) {
        int r = q * FT + t;
        unsigned p = g_pack[r];
        if ((p & 127u) == c) {
            int slot = atomicAdd(&S.cnt, 1);
            if (slot < CAP)
                S.keys[slot] = ((unsigned long long)g_skey[r] << 32) | p;
        }
    }
    __syncthreads();
    int m = min(S.cnt, CAP);
    int mw = (m + 31) >> 5;

    // bitonic sort of 512 u64 keys (ascending == score desc, stable by row)
    for (int k = 2; k <= CAP; k <<= 1) {
        for (int j = k >> 1; j > 0; j >>= 1) {
            if (t < CAP / 2) {
                int i = ((t & ~(j - 1)) << 1) | (t & (j - 1));
                bool up = ((i & k) == 0);
                unsigned long long a = S.keys[i], b = S.keys[i | j];
                if ((a > b) == up) { S.keys[i] = b; S.keys[i | j] = a; }
            }
            __syncthreads();
        }
    }

    // load boxes in sorted order
    if (t < m) {
        int idx = (int)(((unsigned)(S.keys[t] & 0xFFFFFFFFull)) >> 7);
        const float* row = X + (long)idx * ROWLEN;
        float x1 = row[0], y1 = row[1], x2 = row[2], y2 = row[3];
        S.box[t] = make_float4(x1, y1, x2, y2);
        S.area[t] = (x2 - x1) * (y2 - y1);
    }
    for (int p = t; p < m * MW; p += FT) S.mask[p] = 0u;
    __syncthreads();

    // mask[i] = { j > i : IoU(i,j) > 0.5 } — fully parallel over 16 warps
    for (int i = w; i < m; i += FT / 32) {
        float4 bi = S.box[i];
        float ai = S.area[i];
        for (int j = i + 1 + lane; j < m; j += 32) {
            float4 bj = S.box[j];
            float xx1 = fmaxf(bi.x, bj.x);
            float yy1 = fmaxf(bi.y, bj.y);
            float xx2 = fminf(bi.z, bj.z);
            float yy2 = fminf(bi.w, bj.w);
            float ww = fmaxf(xx2 - xx1, 0.0f);
            float hh = fmaxf(yy2 - yy1, 0.0f);
            float inter = ww * hh;
            float iou = inter / (ai + S.area[j] - inter);
            if (iou > 0.5f) atomicOr(&S.mask[i * MW + (j >> 5)], 1u << (j & 31));
        }
    }
    __syncthreads();

    // serial greedy bit-merge (warp 0; lane l owns suppression word l)
    if (w == 0) {
        unsigned sw = 0;
        for (int i = 0; i < m; i++) {
            unsigned word = __shfl_sync(0xffffffffu, sw, i >> 5);
            if (!((word >> (i & 31)) & 1u)) {
                if (lane < mw) sw |= S.mask[i * MW + lane];
            }
        }
        if (lane < MW) S.sup[lane] = sw;
    }
    __syncthreads();

    if (t < m) {
        int idx = (int)(((unsigned)(S.keys[t] & 0xFFFFFFFFull)) >> 7);
        g_keepf[idx] = ((S.sup[t >> 5] >> (t & 31)) & 1u) ? 0.0f : 1.0f;
    }
}

// ---------------------------------------------------------------------------
// K3: scatter — read X linearly (coalesced), write to sorted position.
// rank/keepf/X loads are mutually independent -> depth-1 latency chain.
// ---------------------------------------------------------------------------
__global__ void scatter_kernel(const float* __restrict__ X, float* __restrict__ out) {
    int e = blockIdx.x * blockDim.x + threadIdx.x;
    if (e >= N * ROWLEN) return;
    int row = e / ROWLEN;
    int col = e - row * ROWLEN;
    float v = X[e] * __ldg(&g_keepf[row]);
    out[(long)__ldg(&g_rank[row]) * ROWLEN + col] = v;
}

// ---------------------------------------------------------------------------
extern "C" void kernel_launch(void* const* d_in, const int* in_sizes, int n_in,
                              void* d_out, int out_size) {
    const float* X = (const float*)d_in[0];
    float* out = (float*)d_out;

    int sort_bytes = (int)sizeof(BlockSortT::TempStorage);
    int nms_bytes = (int)sizeof(NmsShared);
    int smem = sort_bytes > nms_bytes ? sort_bytes : nms_bytes;

    static int smem_set = 0;
    if (!smem_set) {
        cudaFuncSetAttribute(sortnms_kernel,
                             cudaFuncAttributeMaxDynamicSharedMemorySize, smem);
        smem_set = 1;
    }

    score_kernel<<<N / 8, 256>>>(X);
    sortnms_kernel<<<NCLS + 1, FT, smem>>>(X);

    const int total = N * ROWLEN;
    scatter_kernel<<<(total + 255) / 256, 256>>>(X, out);
}